// round 1
// baseline (speedup 1.0000x reference)
#include <cuda_runtime.h>
#include <cstdint>

// Problem constants (fixed shapes from setup_inputs)
static constexpr int B_    = 8;
static constexpr int C_    = 256;
static constexpr int N_    = 1024;   // T*H*W = 16*8*8
static constexpr int HEADS = 8;
static constexpr int DK    = 1024;   // KC / heads
static constexpr int DV    = 64;     // VC / heads
static constexpr int KC    = 8192;
static constexpr int VC    = 512;
static constexpr int CHUNKSZ = 128;
static constexpr int NCHUNK  = 8;    // N / CHUNK

// Device scratch (no cudaMalloc allowed)
__device__ float g_k [(size_t)B_ * KC * N_];   // [B][KC][N]   256 MB
__device__ float g_q [(size_t)B_ * KC * N_];   // [B][KC][N]   256 MB
__device__ float g_v [(size_t)B_ * VC * N_];   // [B][VC][N]    16 MB
__device__ float g_o2[(size_t)B_ * VC * N_];   // [B][VC][N]    16 MB

// ---------------------------------------------------------------------------
// Generic batched SGEMM: Out[b] (MxN) = W (MxK) @ X[b] (KxN) [+ bias]
// BM=BN=128, BK=16, 256 threads, 8x8 per-thread micro-tile.
// Requires M%128==0, N%128==0, K%16==0 (true for all our shapes).
// ---------------------------------------------------------------------------
__global__ __launch_bounds__(256, 2)
void sgemm_kernel(const float* __restrict__ W, const float* __restrict__ X,
                  float* __restrict__ Out, const float* __restrict__ bias,
                  int M, int K, int N, long long strideXb, long long strideOb)
{
    __shared__ float Ws[16][132];
    __shared__ float Xs[16][132];

    const int b  = blockIdx.z;
    const float* Xb = X + (size_t)b * strideXb;
    float*       Ob = Out + (size_t)b * strideOb;
    const int m0 = blockIdx.y * 128;
    const int n0 = blockIdx.x * 128;
    const int tid = threadIdx.x;
    const int tx = tid & 15;     // 0..15 -> 8 cols each
    const int ty = tid >> 4;     // 0..15 -> 8 rows each

    float acc[8][8];
#pragma unroll
    for (int i = 0; i < 8; ++i)
#pragma unroll
        for (int j = 0; j < 8; ++j) acc[i][j] = 0.f;

    for (int k0 = 0; k0 < K; k0 += 16) {
        // W tile [128 m][16 k] -> Ws[k][m] (transposed store)
#pragma unroll
        for (int it = 0; it < 2; ++it) {
            int idx = it * 256 + tid;
            int m   = idx >> 2;
            int kq  = (idx & 3) * 4;
            float4 w4 = *reinterpret_cast<const float4*>(W + (size_t)(m0 + m) * K + k0 + kq);
            Ws[kq + 0][m] = w4.x;
            Ws[kq + 1][m] = w4.y;
            Ws[kq + 2][m] = w4.z;
            Ws[kq + 3][m] = w4.w;
        }
        // X tile [16 k][128 n] -> Xs direct
#pragma unroll
        for (int it = 0; it < 2; ++it) {
            int idx = it * 256 + tid;
            int kk  = idx >> 5;
            int nq  = (idx & 31) * 4;
            *reinterpret_cast<float4*>(&Xs[kk][nq]) =
                *reinterpret_cast<const float4*>(Xb + (size_t)(k0 + kk) * N + n0 + nq);
        }
        __syncthreads();

#pragma unroll
        for (int kk = 0; kk < 16; ++kk) {
            float a[8], bb[8];
            *reinterpret_cast<float4*>(a)      = *reinterpret_cast<const float4*>(&Ws[kk][ty * 8]);
            *reinterpret_cast<float4*>(a + 4)  = *reinterpret_cast<const float4*>(&Ws[kk][ty * 8 + 4]);
            *reinterpret_cast<float4*>(bb)     = *reinterpret_cast<const float4*>(&Xs[kk][tx * 8]);
            *reinterpret_cast<float4*>(bb + 4) = *reinterpret_cast<const float4*>(&Xs[kk][tx * 8 + 4]);
#pragma unroll
            for (int i = 0; i < 8; ++i)
#pragma unroll
                for (int j = 0; j < 8; ++j)
                    acc[i][j] = fmaf(a[i], bb[j], acc[i][j]);
        }
        __syncthreads();
    }

#pragma unroll
    for (int i = 0; i < 8; ++i) {
        int m = m0 + ty * 8 + i;
        float bv = bias ? bias[m] : 0.f;
#pragma unroll
        for (int j = 0; j < 8; j += 4) {
            float4 o;
            o.x = acc[i][j + 0] + bv;
            o.y = acc[i][j + 1] + bv;
            o.z = acc[i][j + 2] + bv;
            o.w = acc[i][j + 3] + bv;
            *reinterpret_cast<float4*>(Ob + (size_t)m * N + n0 + tx * 8 + j) = o;
        }
    }
}

// ---------------------------------------------------------------------------
// Fused attention kernel: one CTA per (chunk, head, batch).
// For each i-tile (128 rows of dk):
//   Phase A: S[128,128] = K[i-tile,:1024] @ Q[:1024, chunk]   (fp32 SIMT GEMM)
//   softmax along the 128 chunk columns per row (the chunk == the j tile!)
//   Phase B: O[64,128]  += V[:, i-tile] @ attn[128,128]
// ---------------------------------------------------------------------------
__global__ __launch_bounds__(256, 1)
void attn_kernel()
{
    extern __shared__ float sm[];
    float* Ks = sm;                      // [16][132]
    float* Qs = sm + 16 * 132;           // [16][132]
    float* Sa = sm + 2 * 16 * 132;       // [128][132]  attention tile
    float* Vs = Sa + 128 * 132;          // [64][132]   V tile

    const int chunk = blockIdx.x;
    const int h     = blockIdx.y;
    const int b     = blockIdx.z;

    const float* Kp = g_k + (size_t)(b * HEADS + h) * DK * N_;   // [1024 i][1024 m]
    const float* Qp = g_q + (size_t)(b * HEADS + h) * DK * N_;   // [1024 m][1024 j]
    const float* Vp = g_v + ((size_t)b * VC + h * DV) * N_;      // [64 d][1024 i]
    float*       Op = g_o2 + ((size_t)b * VC + h * DV) * N_ + chunk * CHUNKSZ;

    const int j0 = chunk * CHUNKSZ;
    const int tid = threadIdx.x;
    const int tx = tid & 15;   // 8 cols (j)
    const int ty = tid >> 4;   // phase A: 8 rows (i); phase B: 4 rows (d)

    const float scale = 0.03125f;  // 1/sqrt(1024)

    float Oacc[4][8];
#pragma unroll
    for (int d = 0; d < 4; ++d)
#pragma unroll
        for (int c = 0; c < 8; ++c) Oacc[d][c] = 0.f;

    for (int it = 0; it < 8; ++it) {
        const int i0 = it * 128;

        // ---------- Phase A: scores tile ----------
        float S[8][8];
#pragma unroll
        for (int r = 0; r < 8; ++r)
#pragma unroll
            for (int c = 0; c < 8; ++c) S[r][c] = 0.f;

        for (int m0 = 0; m0 < 1024; m0 += 16) {
            // K tile [128 i][16 m] -> Ks[m][i]
#pragma unroll
            for (int itr = 0; itr < 2; ++itr) {
                int idx = itr * 256 + tid;
                int i   = idx >> 2;
                int mq  = (idx & 3) * 4;
                float4 k4 = *reinterpret_cast<const float4*>(Kp + (size_t)(i0 + i) * N_ + m0 + mq);
                Ks[(mq + 0) * 132 + i] = k4.x;
                Ks[(mq + 1) * 132 + i] = k4.y;
                Ks[(mq + 2) * 132 + i] = k4.z;
                Ks[(mq + 3) * 132 + i] = k4.w;
            }
            // Q tile [16 m][128 j] direct
#pragma unroll
            for (int itr = 0; itr < 2; ++itr) {
                int idx = itr * 256 + tid;
                int kk  = idx >> 5;
                int nq  = (idx & 31) * 4;
                *reinterpret_cast<float4*>(&Qs[kk * 132 + nq]) =
                    *reinterpret_cast<const float4*>(Qp + (size_t)(m0 + kk) * N_ + j0 + nq);
            }
            __syncthreads();

#pragma unroll
            for (int kk = 0; kk < 16; ++kk) {
                float a[8], bb[8];
                *reinterpret_cast<float4*>(a)      = *reinterpret_cast<const float4*>(&Ks[kk * 132 + ty * 8]);
                *reinterpret_cast<float4*>(a + 4)  = *reinterpret_cast<const float4*>(&Ks[kk * 132 + ty * 8 + 4]);
                *reinterpret_cast<float4*>(bb)     = *reinterpret_cast<const float4*>(&Qs[kk * 132 + tx * 8]);
                *reinterpret_cast<float4*>(bb + 4) = *reinterpret_cast<const float4*>(&Qs[kk * 132 + tx * 8 + 4]);
#pragma unroll
                for (int r = 0; r < 8; ++r)
#pragma unroll
                    for (int c = 0; c < 8; ++c)
                        S[r][c] = fmaf(a[r], bb[c], S[r][c]);
            }
            __syncthreads();
        }

        // ---------- Softmax per row over the 128 chunk columns ----------
        // Row r lives in the 16 threads sharing ty (lanes (ty&1)*16 + tx).
#pragma unroll
        for (int r = 0; r < 8; ++r) {
            float mx = -1e30f;
#pragma unroll
            for (int c = 0; c < 8; ++c) { S[r][c] *= scale; mx = fmaxf(mx, S[r][c]); }
#pragma unroll
            for (int off = 8; off >= 1; off >>= 1)
                mx = fmaxf(mx, __shfl_xor_sync(0xffffffffu, mx, off));
            float sum = 0.f;
#pragma unroll
            for (int c = 0; c < 8; ++c) { S[r][c] = __expf(S[r][c] - mx); sum += S[r][c]; }
#pragma unroll
            for (int off = 8; off >= 1; off >>= 1)
                sum += __shfl_xor_sync(0xffffffffu, sum, off);
            float inv = 1.0f / sum;
#pragma unroll
            for (int c = 0; c < 8; ++c) S[r][c] *= inv;
        }

        // ---------- Stage attn to smem + load V tile ----------
#pragma unroll
        for (int r = 0; r < 8; ++r)
#pragma unroll
            for (int c = 0; c < 8; c += 4) {
                float4 o;
                o.x = S[r][c + 0]; o.y = S[r][c + 1]; o.z = S[r][c + 2]; o.w = S[r][c + 3];
                *reinterpret_cast<float4*>(&Sa[(ty * 8 + r) * 132 + tx * 8 + c]) = o;
            }
#pragma unroll
        for (int itr = 0; itr < 8; ++itr) {
            int idx = itr * 256 + tid;
            int d   = idx >> 5;
            int cq  = (idx & 31) * 4;
            *reinterpret_cast<float4*>(&Vs[d * 132 + cq]) =
                *reinterpret_cast<const float4*>(Vp + (size_t)d * N_ + i0 + cq);
        }
        __syncthreads();

        // ---------- Phase B: O += V_tile @ attn ----------
#pragma unroll 4
        for (int kk = 0; kk < 128; ++kk) {
            float bb[8];
            *reinterpret_cast<float4*>(bb)     = *reinterpret_cast<const float4*>(&Sa[kk * 132 + tx * 8]);
            *reinterpret_cast<float4*>(bb + 4) = *reinterpret_cast<const float4*>(&Sa[kk * 132 + tx * 8 + 4]);
#pragma unroll
            for (int dd = 0; dd < 4; ++dd) {
                float av = Vs[(ty * 4 + dd) * 132 + kk];
#pragma unroll
                for (int c = 0; c < 8; ++c)
                    Oacc[dd][c] = fmaf(av, bb[c], Oacc[dd][c]);
            }
        }
        __syncthreads();
    }

    // write O tile [64 d][128 j]
#pragma unroll
    for (int dd = 0; dd < 4; ++dd)
#pragma unroll
        for (int c = 0; c < 8; c += 4) {
            float4 o;
            o.x = Oacc[dd][c + 0]; o.y = Oacc[dd][c + 1];
            o.z = Oacc[dd][c + 2]; o.w = Oacc[dd][c + 3];
            *reinterpret_cast<float4*>(Op + (size_t)(ty * 4 + dd) * N_ + tx * 8 + c) = o;
        }
}

// ---------------------------------------------------------------------------
// Launch
// ---------------------------------------------------------------------------
extern "C" void kernel_launch(void* const* d_in, const int* in_sizes, int n_in,
                              void* d_out, int out_size)
{
    const float* x  = (const float*)d_in[0];
    const float* Wk = (const float*)d_in[1];
    const float* Wq = (const float*)d_in[2];
    const float* Wv = (const float*)d_in[3];
    const float* Wr = (const float*)d_in[4];
    const float* br = (const float*)d_in[5];
    float* out = (float*)d_out;

    float *gk, *gq, *gv, *go2;
    cudaGetSymbolAddress((void**)&gk,  g_k);
    cudaGetSymbolAddress((void**)&gq,  g_q);
    cudaGetSymbolAddress((void**)&gv,  g_v);
    cudaGetSymbolAddress((void**)&go2, g_o2);

    const long long sX = (long long)C_ * N_;     // x batch stride
    const long long sO2 = (long long)VC * N_;

    dim3 blk(256);

    // k = Wk @ x  : [B][8192][1024]
    sgemm_kernel<<<dim3(N_ / 128, KC / 128, B_), blk>>>(
        Wk, x, gk, nullptr, KC, C_, N_, sX, (long long)KC * N_);
    // q = Wq @ x
    sgemm_kernel<<<dim3(N_ / 128, KC / 128, B_), blk>>>(
        Wq, x, gq, nullptr, KC, C_, N_, sX, (long long)KC * N_);
    // v = Wv @ x  : [B][512][1024]
    sgemm_kernel<<<dim3(N_ / 128, VC / 128, B_), blk>>>(
        Wv, x, gv, nullptr, VC, C_, N_, sX, sO2);

    // fused scores -> chunked softmax -> V @ attn
    const int smem_bytes = (2 * 16 * 132 + 128 * 132 + 64 * 132) * (int)sizeof(float);
    cudaFuncSetAttribute(attn_kernel, cudaFuncAttributeMaxDynamicSharedMemorySize, smem_bytes);
    attn_kernel<<<dim3(NCHUNK, HEADS, B_), blk, smem_bytes>>>();

    // y = Wr @ o2 + br : [B][256][1024]
    sgemm_kernel<<<dim3(N_ / 128, C_ / 128, B_), blk>>>(
        Wr, go2, out, br, C_, VC, N_, sO2, (long long)C_ * N_);
}

// round 2
// speedup vs baseline: 3.1625x; 3.1625x over previous
#include <cuda_runtime.h>
#include <cstdint>

// Problem constants (fixed shapes from setup_inputs)
static constexpr int B_    = 8;
static constexpr int C_    = 256;
static constexpr int N_    = 1024;   // T*H*W
static constexpr int HEADS = 8;
static constexpr int DK    = 1024;   // KC / heads
static constexpr int DV    = 64;     // VC / heads
static constexpr int KC    = 8192;
static constexpr int VC    = 512;
static constexpr int CHUNKSZ = 128;
static constexpr int NCHUNK  = 8;

// Device scratch (no cudaMalloc allowed)
__device__ float g_A [(size_t)B_ * HEADS * C_ * C_];    // [b,h][256][256]   16 MB
__device__ float g_P [(size_t)B_ * HEADS * DK * C_];    // [b,h][1024][256]  64 MB
__device__ float g_v [(size_t)B_ * VC * N_];            // [b][512][1024]    16 MB
__device__ float g_o2[(size_t)B_ * VC * N_];            // [b][512][1024]    16 MB

// ---------------------------------------------------------------------------
// Generalized batched SGEMM: Out[z] (MxN) = W[z] (MxK) @ X[z] (KxN) [+ bias]
// z = blockIdx.z decoded as (b = z>>hbits, h = z & mask); per-operand (b,h)
// strides allow batching over b, h, or both.
// BM=BN=128, BK=16, 256 threads, 8x8 per-thread micro-tile.
// Requires M%128==0, N%128==0, K%16==0.
// ---------------------------------------------------------------------------
__global__ __launch_bounds__(256, 2)
void sgemm2_kernel(const float* __restrict__ W, const float* __restrict__ X,
                   float* __restrict__ Out, const float* __restrict__ bias,
                   int M, int K, int N, int hbits,
                   long long sWb, long long sWh,
                   long long sXb, long long sXh,
                   long long sOb, long long sOh)
{
    __shared__ float Ws[16][132];
    __shared__ float Xs[16][132];

    const int z = blockIdx.z;
    const int b = z >> hbits;
    const int h = z & ((1 << hbits) - 1);
    const float* Wp = W + (size_t)b * sWb + (size_t)h * sWh;
    const float* Xp = X + (size_t)b * sXb + (size_t)h * sXh;
    float*       Op = Out + (size_t)b * sOb + (size_t)h * sOh;

    const int m0 = blockIdx.y * 128;
    const int n0 = blockIdx.x * 128;
    const int tid = threadIdx.x;
    const int tx = tid & 15;
    const int ty = tid >> 4;

    float acc[8][8];
#pragma unroll
    for (int i = 0; i < 8; ++i)
#pragma unroll
        for (int j = 0; j < 8; ++j) acc[i][j] = 0.f;

    for (int k0 = 0; k0 < K; k0 += 16) {
        // W tile [128 m][16 k] -> Ws[k][m] (transposed store)
#pragma unroll
        for (int it = 0; it < 2; ++it) {
            int idx = it * 256 + tid;
            int m   = idx >> 2;
            int kq  = (idx & 3) * 4;
            float4 w4 = *reinterpret_cast<const float4*>(Wp + (size_t)(m0 + m) * K + k0 + kq);
            Ws[kq + 0][m] = w4.x;
            Ws[kq + 1][m] = w4.y;
            Ws[kq + 2][m] = w4.z;
            Ws[kq + 3][m] = w4.w;
        }
        // X tile [16 k][128 n] direct
#pragma unroll
        for (int it = 0; it < 2; ++it) {
            int idx = it * 256 + tid;
            int kk  = idx >> 5;
            int nq  = (idx & 31) * 4;
            *reinterpret_cast<float4*>(&Xs[kk][nq]) =
                *reinterpret_cast<const float4*>(Xp + (size_t)(k0 + kk) * N + n0 + nq);
        }
        __syncthreads();

#pragma unroll
        for (int kk = 0; kk < 16; ++kk) {
            float a[8], bb[8];
            *reinterpret_cast<float4*>(a)      = *reinterpret_cast<const float4*>(&Ws[kk][ty * 8]);
            *reinterpret_cast<float4*>(a + 4)  = *reinterpret_cast<const float4*>(&Ws[kk][ty * 8 + 4]);
            *reinterpret_cast<float4*>(bb)     = *reinterpret_cast<const float4*>(&Xs[kk][tx * 8]);
            *reinterpret_cast<float4*>(bb + 4) = *reinterpret_cast<const float4*>(&Xs[kk][tx * 8 + 4]);
#pragma unroll
            for (int i = 0; i < 8; ++i)
#pragma unroll
                for (int j = 0; j < 8; ++j)
                    acc[i][j] = fmaf(a[i], bb[j], acc[i][j]);
        }
        __syncthreads();
    }

#pragma unroll
    for (int i = 0; i < 8; ++i) {
        int m = m0 + ty * 8 + i;
        float bv = bias ? bias[m] : 0.f;
#pragma unroll
        for (int j = 0; j < 8; j += 4) {
            float4 o;
            o.x = acc[i][j + 0] + bv;
            o.y = acc[i][j + 1] + bv;
            o.z = acc[i][j + 2] + bv;
            o.w = acc[i][j + 3] + bv;
            *reinterpret_cast<float4*>(Op + (size_t)m * N + n0 + tx * 8 + j) = o;
        }
    }
}

// ---------------------------------------------------------------------------
// Fused attention kernel: one CTA per (chunk, head, batch).
// For each i-tile (128 rows of dk):
//   Phase A: S[128,128] = P[i-tile, :256] @ x_b[:256, j-chunk]   (K = 256!)
//   softmax along the 128 chunk columns per row
//   Phase B: O[64,128]  += V[:, i-tile] @ attn[128,128]
// ---------------------------------------------------------------------------
__global__ __launch_bounds__(256, 1)
void attn_kernel(const float* __restrict__ x)
{
    extern __shared__ float sm[];
    float* Ks = sm;                      // [16][132]
    float* Qs = sm + 16 * 132;           // [16][132]
    float* Sa = sm + 2 * 16 * 132;       // [128][132]
    float* Vs = Sa + 128 * 132;          // [64][132]

    const int chunk = blockIdx.x;
    const int h     = blockIdx.y;
    const int b     = blockIdx.z;

    const float* Pp = g_P + (size_t)(b * HEADS + h) * DK * C_;   // [1024 i][256 c]
    const float* Xp = x + (size_t)b * C_ * N_;                   // [256 c][1024 j]
    const float* Vp = g_v + ((size_t)b * VC + h * DV) * N_;      // [64 d][1024 i]
    float*       Op = g_o2 + ((size_t)b * VC + h * DV) * N_ + chunk * CHUNKSZ;

    const int j0 = chunk * CHUNKSZ;
    const int tid = threadIdx.x;
    const int tx = tid & 15;
    const int ty = tid >> 4;

    const float scale = 0.03125f;  // 1/sqrt(1024)

    float Oacc[4][8];
#pragma unroll
    for (int d = 0; d < 4; ++d)
#pragma unroll
        for (int c = 0; c < 8; ++c) Oacc[d][c] = 0.f;

    for (int it = 0; it < 8; ++it) {
        const int i0 = it * 128;

        // ---------- Phase A: scores tile, K = 256 ----------
        float S[8][8];
#pragma unroll
        for (int r = 0; r < 8; ++r)
#pragma unroll
            for (int c = 0; c < 8; ++c) S[r][c] = 0.f;

        for (int m0 = 0; m0 < C_; m0 += 16) {
            // P tile [128 i][16 c] -> Ks[c][i]
#pragma unroll
            for (int itr = 0; itr < 2; ++itr) {
                int idx = itr * 256 + tid;
                int i   = idx >> 2;
                int mq  = (idx & 3) * 4;
                float4 k4 = *reinterpret_cast<const float4*>(Pp + (size_t)(i0 + i) * C_ + m0 + mq);
                Ks[(mq + 0) * 132 + i] = k4.x;
                Ks[(mq + 1) * 132 + i] = k4.y;
                Ks[(mq + 2) * 132 + i] = k4.z;
                Ks[(mq + 3) * 132 + i] = k4.w;
            }
            // x tile [16 c][128 j] direct
#pragma unroll
            for (int itr = 0; itr < 2; ++itr) {
                int idx = itr * 256 + tid;
                int kk  = idx >> 5;
                int nq  = (idx & 31) * 4;
                *reinterpret_cast<float4*>(&Qs[kk * 132 + nq]) =
                    *reinterpret_cast<const float4*>(Xp + (size_t)(m0 + kk) * N_ + j0 + nq);
            }
            __syncthreads();

#pragma unroll
            for (int kk = 0; kk < 16; ++kk) {
                float a[8], bb[8];
                *reinterpret_cast<float4*>(a)      = *reinterpret_cast<const float4*>(&Ks[kk * 132 + ty * 8]);
                *reinterpret_cast<float4*>(a + 4)  = *reinterpret_cast<const float4*>(&Ks[kk * 132 + ty * 8 + 4]);
                *reinterpret_cast<float4*>(bb)     = *reinterpret_cast<const float4*>(&Qs[kk * 132 + tx * 8]);
                *reinterpret_cast<float4*>(bb + 4) = *reinterpret_cast<const float4*>(&Qs[kk * 132 + tx * 8 + 4]);
#pragma unroll
                for (int r = 0; r < 8; ++r)
#pragma unroll
                    for (int c = 0; c < 8; ++c)
                        S[r][c] = fmaf(a[r], bb[c], S[r][c]);
            }
            __syncthreads();
        }

        // ---------- Softmax per row over the 128 chunk columns ----------
#pragma unroll
        for (int r = 0; r < 8; ++r) {
            float mx = -1e30f;
#pragma unroll
            for (int c = 0; c < 8; ++c) { S[r][c] *= scale; mx = fmaxf(mx, S[r][c]); }
#pragma unroll
            for (int off = 8; off >= 1; off >>= 1)
                mx = fmaxf(mx, __shfl_xor_sync(0xffffffffu, mx, off));
            float sum = 0.f;
#pragma unroll
            for (int c = 0; c < 8; ++c) { S[r][c] = __expf(S[r][c] - mx); sum += S[r][c]; }
#pragma unroll
            for (int off = 8; off >= 1; off >>= 1)
                sum += __shfl_xor_sync(0xffffffffu, sum, off);
            float inv = 1.0f / sum;
#pragma unroll
            for (int c = 0; c < 8; ++c) S[r][c] *= inv;
        }

        // ---------- Stage attn to smem + load V tile ----------
#pragma unroll
        for (int r = 0; r < 8; ++r)
#pragma unroll
            for (int c = 0; c < 8; c += 4) {
                float4 o;
                o.x = S[r][c + 0]; o.y = S[r][c + 1]; o.z = S[r][c + 2]; o.w = S[r][c + 3];
                *reinterpret_cast<float4*>(&Sa[(ty * 8 + r) * 132 + tx * 8 + c]) = o;
            }
#pragma unroll
        for (int itr = 0; itr < 8; ++itr) {
            int idx = itr * 256 + tid;
            int d   = idx >> 5;
            int cq  = (idx & 31) * 4;
            *reinterpret_cast<float4*>(&Vs[d * 132 + cq]) =
                *reinterpret_cast<const float4*>(Vp + (size_t)d * N_ + i0 + cq);
        }
        __syncthreads();

        // ---------- Phase B: O += V_tile @ attn ----------
#pragma unroll 4
        for (int kk = 0; kk < 128; ++kk) {
            float bb[8];
            *reinterpret_cast<float4*>(bb)     = *reinterpret_cast<const float4*>(&Sa[kk * 132 + tx * 8]);
            *reinterpret_cast<float4*>(bb + 4) = *reinterpret_cast<const float4*>(&Sa[kk * 132 + tx * 8 + 4]);
#pragma unroll
            for (int dd = 0; dd < 4; ++dd) {
                float av = Vs[(ty * 4 + dd) * 132 + kk];
#pragma unroll
                for (int c = 0; c < 8; ++c)
                    Oacc[dd][c] = fmaf(av, bb[c], Oacc[dd][c]);
            }
        }
        __syncthreads();
    }

    // write O tile [64 d][128 j]
#pragma unroll
    for (int dd = 0; dd < 4; ++dd)
#pragma unroll
        for (int c = 0; c < 8; c += 4) {
            float4 o;
            o.x = Oacc[dd][c + 0]; o.y = Oacc[dd][c + 1];
            o.z = Oacc[dd][c + 2]; o.w = Oacc[dd][c + 3];
            *reinterpret_cast<float4*>(Op + (size_t)(ty * 4 + dd) * N_ + tx * 8 + c) = o;
        }
}

// ---------------------------------------------------------------------------
// Launch
// ---------------------------------------------------------------------------
extern "C" void kernel_launch(void* const* d_in, const int* in_sizes, int n_in,
                              void* d_out, int out_size)
{
    const float* x  = (const float*)d_in[0];
    const float* Wk = (const float*)d_in[1];
    const float* Wq = (const float*)d_in[2];
    const float* Wv = (const float*)d_in[3];
    const float* Wr = (const float*)d_in[4];
    const float* br = (const float*)d_in[5];
    float* out = (float*)d_out;

    float *gA, *gP, *gv, *go2;
    cudaGetSymbolAddress((void**)&gA,  g_A);
    cudaGetSymbolAddress((void**)&gP,  g_P);
    cudaGetSymbolAddress((void**)&gv,  g_v);
    cudaGetSymbolAddress((void**)&go2, g_o2);

    dim3 blk(256);

    // A[b,h] = x_b (256x1024) @ Wq_h (1024x256)  -> [64][256][256]
    sgemm2_kernel<<<dim3(C_ / 128, C_ / 128, B_ * HEADS), blk>>>(
        x, Wq, gA, nullptr,
        /*M=*/C_, /*K=*/N_, /*N=*/C_, /*hbits=*/3,
        /*sWb=*/(long long)C_ * N_, /*sWh=*/0,
        /*sXb=*/0, /*sXh=*/(long long)DK * C_,
        /*sOb=*/(long long)HEADS * C_ * C_, /*sOh=*/(long long)C_ * C_);

    // P[b,h] = Wk_h (1024x256) @ A[b,h] (256x256) -> [64][1024][256]
    sgemm2_kernel<<<dim3(C_ / 128, DK / 128, B_ * HEADS), blk>>>(
        Wk, gA, gP, nullptr,
        /*M=*/DK, /*K=*/C_, /*N=*/C_, /*hbits=*/3,
        /*sWb=*/0, /*sWh=*/(long long)DK * C_,
        /*sXb=*/(long long)HEADS * C_ * C_, /*sXh=*/(long long)C_ * C_,
        /*sOb=*/(long long)HEADS * DK * C_, /*sOh=*/(long long)DK * C_);

    // v = Wv @ x_b : [B][512][1024]
    sgemm2_kernel<<<dim3(N_ / 128, VC / 128, B_), blk>>>(
        Wv, x, gv, nullptr,
        /*M=*/VC, /*K=*/C_, /*N=*/N_, /*hbits=*/0,
        /*sWb=*/0, /*sWh=*/0,
        /*sXb=*/(long long)C_ * N_, /*sXh=*/0,
        /*sOb=*/(long long)VC * N_, /*sOh=*/0);

    // fused scores(K=256) -> chunked softmax -> V @ attn
    const int smem_bytes = (2 * 16 * 132 + 128 * 132 + 64 * 132) * (int)sizeof(float);
    cudaFuncSetAttribute(attn_kernel, cudaFuncAttributeMaxDynamicSharedMemorySize, smem_bytes);
    attn_kernel<<<dim3(NCHUNK, HEADS, B_), blk, smem_bytes>>>(x);

    // y = Wr @ o2 + br : [B][256][1024]
    sgemm2_kernel<<<dim3(N_ / 128, C_ / 128, B_), blk>>>(
        Wr, go2, out, br,
        /*M=*/C_, /*K=*/VC, /*N=*/N_, /*hbits=*/0,
        /*sWb=*/0, /*sWh=*/0,
        /*sXb=*/(long long)VC * N_, /*sXh=*/0,
        /*sOb=*/(long long)C_ * N_, /*sOh=*/0);
}